// round 6
// baseline (speedup 1.0000x reference)
#include <cuda_runtime.h>

// SoftDepthShader: per-pixel softmax depth blend over K=50 raster slots.
// out[p] = (sum_k w_k * z_k + delta) / (sum_k w_k + delta)
//   mask_k = pix_to_face_k >= 0  (int32 on device)
//   prob_k = sigmoid(-dists_k/SIGMA) * mask_k
//   zinv_k = (ZFAR - z_k)/(ZFAR-ZNEAR) * mask_k
//   zmax   = max(max_k zinv_k, EPS)
//   w_k    = prob_k * exp((zinv_k - zmax)/GAMMA)
//   delta  = max(exp((EPS - zmax)/GAMMA), EPS)
//
// R6: 2 pixels per 8-lane group to double per-warp independent loads
// (raise in-flight sector count / achieved DRAM BW). float2 loads, fast
// reciprocal sigmoid, z reconstructed from zinv in pass 2, fused float2 store.

#define KSLOTS   50
#define SLOT2    25      // float2 slots per pixel
#define LANES_PP 8
#define SPL      4       // float2 slots per lane per pixel

__global__ __launch_bounds__(256)
void soft_depth_kernel(const float2* __restrict__ zbuf,
                       const float2* __restrict__ dists,
                       const int2*   __restrict__ p2f,
                       float2* __restrict__ out,
                       int npair)
{
    const float INV_SIGMA  = 1e4f;
    const float INV_GAMMA  = 1e4f;
    const float ZFAR       = 100.0f;
    const float ZRANGE     = 99.0f;
    const float INV_ZRANGE = 1.0f / 99.0f;
    const float EPS        = 1e-10f;

    int tid = blockIdx.x * blockDim.x + threadIdx.x;
    int grp = tid >> 3;         // one 8-lane group handles a pixel pair
    int sub = tid & 7;
    if (grp >= npair) return;

    size_t baseA = (size_t)grp * (2 * SLOT2);
    size_t baseB = baseA + SLOT2;

    float prA[2*SPL], ziA[2*SPL];
    float prB[2*SPL], ziB[2*SPL];
    float zmaxA = 0.0f, zmaxB = 0.0f;

    #pragma unroll
    for (int i = 0; i < SPL; i++) {
        int s = sub + LANES_PP * i;
        bool in = (s < SLOT2);

        float2 zA = make_float2(0.f, 0.f), dA = make_float2(0.f, 0.f);
        int2   fA = make_int2(-1, -1);
        float2 zB = make_float2(0.f, 0.f), dB = make_float2(0.f, 0.f);
        int2   fB = make_int2(-1, -1);
        if (in) {
            zA = __ldcs(zbuf  + baseA + s);
            dA = __ldcs(dists + baseA + s);
            fA = __ldcs(p2f   + baseA + s);
            zB = __ldcs(zbuf  + baseB + s);
            dB = __ldcs(dists + baseB + s);
            fB = __ldcs(p2f   + baseB + s);
        }

        // pixel A
        {
            float m0 = (fA.x >= 0) ? 1.0f : 0.0f;
            float m1 = (fA.y >= 0) ? 1.0f : 0.0f;
            float p0 = m0 * __fdividef(1.0f, 1.0f + __expf(dA.x * INV_SIGMA));
            float p1 = m1 * __fdividef(1.0f, 1.0f + __expf(dA.y * INV_SIGMA));
            float v0 = (ZFAR - zA.x) * INV_ZRANGE * m0;
            float v1 = (ZFAR - zA.y) * INV_ZRANGE * m1;
            prA[2*i] = p0;  ziA[2*i] = v0;
            prA[2*i+1] = p1; ziA[2*i+1] = v1;
            zmaxA = fmaxf(zmaxA, fmaxf(v0, v1));
        }
        // pixel B
        {
            float m0 = (fB.x >= 0) ? 1.0f : 0.0f;
            float m1 = (fB.y >= 0) ? 1.0f : 0.0f;
            float p0 = m0 * __fdividef(1.0f, 1.0f + __expf(dB.x * INV_SIGMA));
            float p1 = m1 * __fdividef(1.0f, 1.0f + __expf(dB.y * INV_SIGMA));
            float v0 = (ZFAR - zB.x) * INV_ZRANGE * m0;
            float v1 = (ZFAR - zB.y) * INV_ZRANGE * m1;
            prB[2*i] = p0;  ziB[2*i] = v0;
            prB[2*i+1] = p1; ziB[2*i+1] = v1;
            zmaxB = fmaxf(zmaxB, fmaxf(v0, v1));
        }
    }

    // 8-lane group max for both pixels
    #pragma unroll
    for (int o = 4; o; o >>= 1) {
        zmaxA = fmaxf(zmaxA, __shfl_xor_sync(0xffffffffu, zmaxA, o));
        zmaxB = fmaxf(zmaxB, __shfl_xor_sync(0xffffffffu, zmaxB, o));
    }
    zmaxA = fmaxf(zmaxA, EPS);
    zmaxB = fmaxf(zmaxB, EPS);

    float numA = 0.0f, denA = 0.0f, numB = 0.0f, denB = 0.0f;
    #pragma unroll
    for (int j = 0; j < 2*SPL; j++) {
        float wA = prA[j] * __expf((ziA[j] - zmaxA) * INV_GAMMA);
        float zA = fmaf(-ziA[j], ZRANGE, ZFAR);  // reconstruct z; w=0 if masked
        denA += wA;
        numA = fmaf(wA, zA, numA);

        float wB = prB[j] * __expf((ziB[j] - zmaxB) * INV_GAMMA);
        float zB = fmaf(-ziB[j], ZRANGE, ZFAR);
        denB += wB;
        numB = fmaf(wB, zB, numB);
    }
    #pragma unroll
    for (int o = 4; o; o >>= 1) {
        denA += __shfl_xor_sync(0xffffffffu, denA, o);
        numA += __shfl_xor_sync(0xffffffffu, numA, o);
        denB += __shfl_xor_sync(0xffffffffu, denB, o);
        numB += __shfl_xor_sync(0xffffffffu, numB, o);
    }

    if (sub == 0) {
        float deltaA = fmaxf(__expf((EPS - zmaxA) * INV_GAMMA), EPS);
        float deltaB = fmaxf(__expf((EPS - zmaxB) * INV_GAMMA), EPS);
        float2 r;
        r.x = __fdividef(numA + deltaA, denA + deltaA);   // BG_BLUE = 1
        r.y = __fdividef(numB + deltaB, denB + deltaB);
        out[grp] = r;
    }
}

extern "C" void kernel_launch(void* const* d_in, const int* in_sizes, int n_in,
                              void* d_out, int out_size)
{
    const float2* zbuf  = (const float2*)d_in[0];
    const float2* dists = (const float2*)d_in[1];
    const int2*   p2f   = (const int2*)d_in[2];
    float2*       out   = (float2*)d_out;

    int npix  = in_sizes[0] / KSLOTS;              // 8*256*256 = 524288 (even)
    int npair = npix >> 1;                         // 262144
    int threads = 256;
    long long total = (long long)npair * LANES_PP; // 8 threads per pair
    int blocks = (int)((total + threads - 1) / threads);

    soft_depth_kernel<<<blocks, threads>>>(zbuf, dists, p2f, out, npair);
}